// round 5
// baseline (speedup 1.0000x reference)
#include <cuda_runtime.h>
#include <math.h>

#define B_   32
#define T_   48
#define L_   400
#define H2_  512
#define E_   128
#define V_   50000
#define OOV_ 100
#define VEXT_ 50100
#define BT_  (B_*T_)

// ---------------- scratch (static device allocations; no cudaMalloc) ----------------
__device__ float g_Xe[BT_*H2_];
__device__ float g_Xd[BT_*H2_];
__device__ float g_att[BT_*L_];        // e -> temporal -> enc_att (in place)
__device__ float g_s[BT_*T_];          // dec scores -> datt (in place)
__device__ float g_cat[BT_*3*H2_];     // [h | enc_ctx | dec_ctx]
__device__ float g_proj[BT_*E_];
__device__ float g_p[BT_];
__device__ float g_rmax[BT_];
__device__ float g_rsum[BT_];
__device__ float g_logits[(size_t)BT_*V_];   // 307 MB

// ---------------- generic tiled fp32 GEMM: C = A * op(B), row-major ----------------
#define TM 64
#define TN 64
#define TKK 16

__global__ void gemm_k(int M, int N, int K,
                       const float* __restrict__ A, int lda, long long sA,
                       const float* __restrict__ B, int ldb, long long sB, int transB,
                       float* __restrict__ C, int ldc, long long sC)
{
    __shared__ float As[TKK][TM];
    __shared__ float Bs[TKK][TN];
    int bz = blockIdx.z;
    A += (long long)bz * sA;
    B += (long long)bz * sB;
    C += (long long)bz * sC;
    int m0 = blockIdx.y * TM;
    int n0 = blockIdx.x * TN;
    int tid = threadIdx.x;          // 0..255
    int tx = tid & 15, ty = tid >> 4;
    float acc[4][4] = {};

    for (int kk = 0; kk < K; kk += TKK) {
#pragma unroll
        for (int i = 0; i < 4; i++) {
            int li = tid + 256 * i;           // 0..1023
            int m = li & 63;
            int k = li >> 6;                  // 0..15
            int gm = m0 + m, gk = kk + k;
            float v = 0.f;
            if (gm < M && gk < K) v = A[(long long)gm * lda + gk];
            As[k][m] = v;
        }
#pragma unroll
        for (int i = 0; i < 4; i++) {
            int li = tid + 256 * i;
            int n = li & 63;
            int k = li >> 6;
            int gn = n0 + n, gk = kk + k;
            float v = 0.f;
            if (gn < N && gk < K) {
                if (transB) v = B[(long long)gn * ldb + gk];
                else        v = B[(long long)gk * ldb + gn];
            }
            Bs[k][n] = v;
        }
        __syncthreads();
#pragma unroll
        for (int k = 0; k < TKK; k++) {
            float a0[4], b0[4];
#pragma unroll
            for (int i = 0; i < 4; i++) a0[i] = As[k][ty*4 + i];
#pragma unroll
            for (int j = 0; j < 4; j++) b0[j] = Bs[k][tx*4 + j];
#pragma unroll
            for (int i = 0; i < 4; i++)
#pragma unroll
                for (int j = 0; j < 4; j++)
                    acc[i][j] = fmaf(a0[i], b0[j], acc[i][j]);
        }
        __syncthreads();
    }
#pragma unroll
    for (int i = 0; i < 4; i++) {
        int gm = m0 + ty*4 + i;
        if (gm >= M) continue;
#pragma unroll
        for (int j = 0; j < 4; j++) {
            int gn = n0 + tx*4 + j;
            if (gn < N) C[(long long)gm * ldc + gn] = acc[i][j];
        }
    }
}

// ---------------- dedicated vocab GEMM: C[BT,V] = A[BT,E] * B[E,V] ----------------
// 64(M) x 128(N) tile, K chunked by 32, 256 threads, 4x8 microtile.
// Inner loop per k: 3 x LDS.128 + 32 FFMA -> ~1.09x over FFMA issue floor.
#define VM 64
#define VN 128
#define VKC 32

__global__ void __launch_bounds__(256) vocab_gemm_k(
    const float* __restrict__ A,      // (BT, E) row-major
    const float* __restrict__ Bv,     // (E, V) row-major
    float* __restrict__ C)            // (BT, V)
{
    __shared__ float As[VKC][VM];     // 8 KB
    __shared__ float Bs[VKC][VN];     // 16 KB
    int n0 = blockIdx.x * VN;
    int m0 = blockIdx.y * VM;
    int tid = threadIdx.x;
    int tx = tid & 15;                // 16 n-groups of 8 cols
    int ty = tid >> 4;                // 16 m-groups of 4 rows
    float acc[4][8] = {};

    for (int kk = 0; kk < E_; kk += VKC) {
        // A tile: 64 rows x 32 k. Each thread: 2 float4 loads along k.
#pragma unroll
        for (int i = 0; i < 2; i++) {
            int li = tid + 256 * i;           // 0..511
            int m = li & 63;
            int k = (li >> 6) << 2;           // 0,4,..,28
            float4 a4 = *(const float4*)(A + (long long)(m0 + m) * E_ + kk + k);
            As[k+0][m] = a4.x; As[k+1][m] = a4.y; As[k+2][m] = a4.z; As[k+3][m] = a4.w;
        }
        // B tile: 32 k x 128 n. Each thread: 4 float4 loads along n (contiguous).
#pragma unroll
        for (int i = 0; i < 4; i++) {
            int li = tid + 256 * i;           // 0..1023
            int n = (li & 31) << 2;           // 0,4,..,124
            int k = li >> 5;                  // 0..31
            int gn = n0 + n;
            float4 b4 = make_float4(0.f, 0.f, 0.f, 0.f);
            if (gn + 3 < V_) {
                b4 = *(const float4*)(Bv + (long long)(kk + k) * V_ + gn);
            } else {
                float t[4] = {0.f, 0.f, 0.f, 0.f};
                for (int j = 0; j < 4; j++)
                    if (gn + j < V_) t[j] = Bv[(long long)(kk + k) * V_ + gn + j];
                b4 = make_float4(t[0], t[1], t[2], t[3]);
            }
            *(float4*)&Bs[k][n] = b4;
        }
        __syncthreads();
#pragma unroll
        for (int k = 0; k < VKC; k++) {
            float4 a4 = *(const float4*)&As[k][ty*4];
            float4 b4a = *(const float4*)&Bs[k][tx*8];
            float4 b4b = *(const float4*)&Bs[k][tx*8 + 4];
            float a[4] = {a4.x, a4.y, a4.z, a4.w};
            float b[8] = {b4a.x, b4a.y, b4a.z, b4a.w, b4b.x, b4b.y, b4b.z, b4b.w};
#pragma unroll
            for (int i = 0; i < 4; i++)
#pragma unroll
                for (int j = 0; j < 8; j++)
                    acc[i][j] = fmaf(a[i], b[j], acc[i][j]);
        }
        __syncthreads();
    }
#pragma unroll
    for (int i = 0; i < 4; i++) {
        int gm = m0 + ty*4 + i;
#pragma unroll
        for (int j = 0; j < 8; j += 4) {
            int gn = n0 + tx*8 + j;
            if (gn + 3 < V_) {
                *(float4*)(C + (long long)gm * V_ + gn) =
                    make_float4(acc[i][j], acc[i][j+1], acc[i][j+2], acc[i][j+3]);
            } else {
                for (int q = 0; q < 4; q++)
                    if (gn + q < V_) C[(long long)gm * V_ + gn + q] = acc[i][j+q];
            }
        }
    }
}

// ---------------- intra-temporal: exp + running-denominator (prefix over t) --------
__global__ void temporal_k(float* __restrict__ e)
{
    int idx = blockIdx.x * blockDim.x + threadIdx.x;
    if (idx >= B_ * L_) return;
    int b = idx / L_, l = idx % L_;
    float* base = e + (size_t)b * T_ * L_ + l;
    float acc = 0.f;
    for (int t = 0; t < T_; t++) {
        float x = __expf(base[(size_t)t * L_]);
        float denom = (t == 0) ? 1.f : acc;
        base[(size_t)t * L_] = x / denom;
        acc += x;
    }
}

// ---------------- normalize enc attention over L (in place) ----------------
__global__ void encnorm_k(float* __restrict__ att)
{
    int r = blockIdx.x;                // BT rows
    float* row = att + (size_t)r * L_;
    float acc = 0.f;
    for (int i = threadIdx.x; i < L_; i += 128) acc += row[i];
    __shared__ float sh[128];
    sh[threadIdx.x] = acc;
    __syncthreads();
    for (int st = 64; st > 0; st >>= 1) {
        if (threadIdx.x < st) sh[threadIdx.x] += sh[threadIdx.x + st];
        __syncthreads();
    }
    float inv = 1.f / sh[0];
    for (int i = threadIdx.x; i < L_; i += 128) row[i] *= inv;
}

// ---------------- masked causal softmax over previous decoder steps ----------------
__global__ void decsm_k(float* __restrict__ s)
{
    int r = blockIdx.x * blockDim.x + threadIdx.x;
    if (r >= BT_) return;
    int t = r % T_;
    float* row = s + (size_t)r * T_;
    if (t == 0) {
        for (int j = 0; j < T_; j++) row[j] = 0.f;   // dec_ctx forced 0 at t=0
        return;
    }
    float m = -1e30f;
    for (int j = 0; j < t; j++) m = fmaxf(m, row[j]);
    float sum = 0.f;
    for (int j = 0; j < t; j++) { float e = __expf(row[j] - m); row[j] = e; sum += e; }
    float inv = 1.f / sum;
    for (int j = 0; j < t; j++) row[j] *= inv;
    for (int j = t; j < T_; j++) row[j] = 0.f;
}

// ---------------- copy h into cat[:, 0:H2] ----------------
__global__ void copyh_k(const float* __restrict__ dec, float* __restrict__ cat)
{
    int idx = blockIdx.x * blockDim.x + threadIdx.x;
    if (idx >= BT_ * H2_) return;
    int r = idx >> 9, h = idx & 511;
    cat[(size_t)r * (3*H2_) + h] = dec[idx];
}

// ---------------- copy gate p = sigmoid(cat . w_ptr + b) ----------------
__global__ void pgate_k(const float* __restrict__ cat, const float* __restrict__ w,
                        const float* __restrict__ bb, float* __restrict__ p)
{
    int r = blockIdx.x;
    const float* row = cat + (size_t)r * (3*H2_);
    float acc = 0.f;
    for (int i = threadIdx.x; i < 3*H2_; i += 256) acc += row[i] * w[i];
    __shared__ float sh[256];
    sh[threadIdx.x] = acc;
    __syncthreads();
    for (int st = 128; st > 0; st >>= 1) {
        if (threadIdx.x < st) sh[threadIdx.x] += sh[threadIdx.x + st];
        __syncthreads();
    }
    if (threadIdx.x == 0) p[r] = 1.f / (1.f + __expf(-(sh[0] + bb[0])));
}

// ---------------- online row max / sum-exp over V (one pass) ----------------
__global__ void rowstats_k(const float* __restrict__ logits,
                           float* __restrict__ rmax, float* __restrict__ rsum)
{
    int r = blockIdx.x;
    const float4* row = (const float4*)(logits + (size_t)r * V_);
    float m = -1e30f, s = 0.f;
    for (int i = threadIdx.x; i < V_/4; i += blockDim.x) {
        float4 x4 = row[i];
        float xs[4] = {x4.x, x4.y, x4.z, x4.w};
#pragma unroll
        for (int j = 0; j < 4; j++) {
            float x = xs[j];
            if (x > m) { s = s * __expf(m - x) + 1.f; m = x; }
            else       { s += __expf(x - m); }
        }
    }
    __shared__ float sm[256], ss[256];
    sm[threadIdx.x] = m; ss[threadIdx.x] = s;
    __syncthreads();
    for (int st = 128; st > 0; st >>= 1) {
        if (threadIdx.x < st) {
            float m1 = sm[threadIdx.x], s1 = ss[threadIdx.x];
            float m2 = sm[threadIdx.x + st], s2 = ss[threadIdx.x + st];
            float M = fmaxf(m1, m2);
            sm[threadIdx.x] = M;
            ss[threadIdx.x] = s1 * __expf(m1 - M) + s2 * __expf(m2 - M);
        }
        __syncthreads();
    }
    if (threadIdx.x == 0) { rmax[r] = sm[0]; rsum[r] = ss[0]; }
}

// ---------------- final write: (1-p)*softmax into [:, :V], zero OOV tail ----------
// V (=50000) and VEXT (=50100) are both divisible by 4; row bases 16B-aligned.
__global__ void final_k(const float* __restrict__ logits, const float* __restrict__ rmax,
                        const float* __restrict__ rsum, const float* __restrict__ p,
                        float* __restrict__ out)
{
    int r = blockIdx.y;
    int v4 = blockIdx.x * blockDim.x + threadIdx.x;     // float4 index
    if (v4 >= VEXT_/4) return;
    float4 o = make_float4(0.f, 0.f, 0.f, 0.f);
    if (v4 < V_/4) {
        float sc = (1.f - p[r]) / rsum[r];
        float mx = rmax[r];
        float4 x = *(const float4*)(logits + (size_t)r * V_ + v4*4);
        o.x = sc * __expf(x.x - mx);
        o.y = sc * __expf(x.y - mx);
        o.z = sc * __expf(x.z - mx);
        o.w = sc * __expf(x.w - mx);
    }
    *(float4*)(out + (size_t)r * VEXT_ + v4*4) = o;
}

// ---------------- pointer scatter-add: out[r, ev[b,l]] += p[r]*enc_att[r,l] -------
__global__ void scatter_k(const int* __restrict__ ev, const float* __restrict__ att,
                          const float* __restrict__ p, float* __restrict__ out)
{
    int idx = blockIdx.x * blockDim.x + threadIdx.x;
    if (idx >= BT_ * L_) return;
    int l = idx % L_;
    int r = idx / L_;         // r = b*T + t
    int b = r / T_;
    float val = p[r] * att[idx];
    atomicAdd(&out[(size_t)r * VEXT_ + ev[b * L_ + l]], val);
}

// ---------------- host orchestration ----------------
static void gemm(int M, int N, int K,
                 const float* A, int lda, long long sA,
                 const float* B, int ldb, long long sB, int transB,
                 float* C, int ldc, long long sC, int batch)
{
    dim3 grid((N + TN - 1) / TN, (M + TM - 1) / TM, batch);
    gemm_k<<<grid, 256>>>(M, N, K, A, lda, sA, B, ldb, sB, transB, C, ldc, sC);
}

extern "C" void kernel_launch(void* const* d_in, const int* in_sizes, int n_in,
                              void* d_out, int out_size)
{
    const float* dec     = (const float*)d_in[0];   // (B,T,H2)
    const float* enc     = (const float*)d_in[1];   // (B,L,H2)
    const float* W_enc   = (const float*)d_in[2];   // (H2,H2)
    const float* W_dec   = (const float*)d_in[3];   // (H2,H2)
    const float* W_proj  = (const float*)d_in[4];   // (3H2,E)
    const float* W_vocab = (const float*)d_in[5];   // (E,V)
    const float* w_ptr   = (const float*)d_in[6];   // (3H2,)
    const float* b_ptr   = (const float*)d_in[7];   // (1,)
    const int*   ev      = (const int*)d_in[8];     // (B,L)
    float* out = (float*)d_out;                     // (B,T,VEXT)

    float *Xe, *Xd, *att, *s, *cat, *proj, *p, *rmax, *rsum, *logits;
    cudaGetSymbolAddress((void**)&Xe,     g_Xe);
    cudaGetSymbolAddress((void**)&Xd,     g_Xd);
    cudaGetSymbolAddress((void**)&att,    g_att);
    cudaGetSymbolAddress((void**)&s,      g_s);
    cudaGetSymbolAddress((void**)&cat,    g_cat);
    cudaGetSymbolAddress((void**)&proj,   g_proj);
    cudaGetSymbolAddress((void**)&p,      g_p);
    cudaGetSymbolAddress((void**)&rmax,   g_rmax);
    cudaGetSymbolAddress((void**)&rsum,   g_rsum);
    cudaGetSymbolAddress((void**)&logits, g_logits);

    // 1) bilinear projections of decoder hiddens
    gemm(BT_, H2_, H2_, dec, H2_, 0, W_enc, H2_, 0, 0, Xe, H2_, 0, 1);
    gemm(BT_, H2_, H2_, dec, H2_, 0, W_dec, H2_, 0, 0, Xd, H2_, 0, 1);

    // 2) encoder attention scores e[b,t,l] = Xe[b,t,:] . enc[b,l,:]   (batched, B^T)
    gemm(T_, L_, H2_, Xe, H2_, (long long)T_*H2_,
         enc, H2_, (long long)L_*H2_, 1,
         att, L_, (long long)T_*L_, B_);

    // 3) intra-temporal exp + cumulative denominator, then normalize over L
    temporal_k<<<(B_*L_ + 255)/256, 256>>>(att);
    encnorm_k<<<BT_, 128>>>(att);

    // 4) decoder self-attention scores + causal softmax
    gemm(T_, T_, H2_, Xd, H2_, (long long)T_*H2_,
         dec, H2_, (long long)T_*H2_, 1,
         s, T_, (long long)T_*T_, B_);
    decsm_k<<<(BT_ + 127)/128, 128>>>(s);

    // 5) assemble cat = [h | enc_ctx | dec_ctx]
    copyh_k<<<(BT_*H2_ + 255)/256, 256>>>(dec, cat);
    gemm(T_, H2_, L_, att, L_, (long long)T_*L_,
         enc, H2_, (long long)L_*H2_, 0,
         cat + H2_, 3*H2_, (long long)T_*3*H2_, B_);
    gemm(T_, H2_, T_, s, T_, (long long)T_*T_,
         dec, H2_, (long long)T_*H2_, 0,
         cat + 2*H2_, 3*H2_, (long long)T_*3*H2_, B_);

    // 6) copy gate + embedding projection
    pgate_k<<<BT_, 256>>>(cat, w_ptr, b_ptr, p);
    gemm(BT_, E_, 3*H2_, cat, 3*H2_, 0, W_proj, E_, 0, 0, proj, E_, 0, 1);

    // 7) vocab logits (dominant GEMM: 1536 x 50000 x 128) — dedicated kernel
    {
        dim3 grid((V_ + VN - 1) / VN, BT_ / VM);
        vocab_gemm_k<<<grid, 256>>>(proj, W_vocab, logits);
    }

    // 8) softmax stats, final distribution write, pointer scatter
    rowstats_k<<<BT_, 256>>>(logits, rmax, rsum);
    final_k<<<dim3((VEXT_/4 + 255)/256, BT_), 256>>>(logits, rmax, rsum, p, out);
    scatter_k<<<(BT_*L_ + 255)/256, 256>>>(ev, att, p, out);
}

// round 6
// speedup vs baseline: 2.0730x; 2.0730x over previous
#include <cuda_runtime.h>
#include <cuda_bf16.h>
#include <math.h>

#define B_   32
#define T_   48
#define L_   400
#define H2_  512
#define E_   128
#define V_   50000
#define OOV_ 100
#define VEXT_ 50100
#define BT_  (B_*T_)

// ---------------- scratch (static device allocations; no cudaMalloc) ----------------
__device__ float g_Xe[BT_*H2_];
__device__ float g_Xd[BT_*H2_];
__device__ float g_att[BT_*L_];        // e -> temporal -> enc_att (in place)
__device__ float g_s[BT_*T_];          // dec scores -> datt (in place)
__device__ float g_cat[BT_*3*H2_];     // [h | enc_ctx | dec_ctx]
__device__ float g_proj[BT_*E_];
__device__ float g_p[BT_];
__device__ float g_rmax[BT_];
__device__ float g_rsum[BT_];
__device__ float g_logits[(size_t)BT_*V_];            // 307 MB
__device__ __nv_bfloat16 g_A2[(size_t)BT_*3*E_];      // split A: [hi|hi|lo], (BT,384)
__device__ __nv_bfloat16 g_B2t[(size_t)V_*3*E_];      // split B^T: rows [hi;lo;hi], (V,384)

// ---------------- generic tiled fp32 GEMM: C = A * op(B), row-major ----------------
#define TM 64
#define TN 64
#define TKK 16

__global__ void gemm_k(int M, int N, int K,
                       const float* __restrict__ A, int lda, long long sA,
                       const float* __restrict__ B, int ldb, long long sB, int transB,
                       float* __restrict__ C, int ldc, long long sC)
{
    __shared__ float As[TKK][TM];
    __shared__ float Bs[TKK][TN];
    int bz = blockIdx.z;
    A += (long long)bz * sA;
    B += (long long)bz * sB;
    C += (long long)bz * sC;
    int m0 = blockIdx.y * TM;
    int n0 = blockIdx.x * TN;
    int tid = threadIdx.x;          // 0..255
    int tx = tid & 15, ty = tid >> 4;
    float acc[4][4] = {};

    for (int kk = 0; kk < K; kk += TKK) {
#pragma unroll
        for (int i = 0; i < 4; i++) {
            int li = tid + 256 * i;           // 0..1023
            int m = li & 63;
            int k = li >> 6;                  // 0..15
            int gm = m0 + m, gk = kk + k;
            float v = 0.f;
            if (gm < M && gk < K) v = A[(long long)gm * lda + gk];
            As[k][m] = v;
        }
#pragma unroll
        for (int i = 0; i < 4; i++) {
            int li = tid + 256 * i;
            int n = li & 63;
            int k = li >> 6;
            int gn = n0 + n, gk = kk + k;
            float v = 0.f;
            if (gn < N && gk < K) {
                if (transB) v = B[(long long)gn * ldb + gk];
                else        v = B[(long long)gk * ldb + gn];
            }
            Bs[k][n] = v;
        }
        __syncthreads();
#pragma unroll
        for (int k = 0; k < TKK; k++) {
            float a0[4], b0[4];
#pragma unroll
            for (int i = 0; i < 4; i++) a0[i] = As[k][ty*4 + i];
#pragma unroll
            for (int j = 0; j < 4; j++) b0[j] = Bs[k][tx*4 + j];
#pragma unroll
            for (int i = 0; i < 4; i++)
#pragma unroll
                for (int j = 0; j < 4; j++)
                    acc[i][j] = fmaf(a0[i], b0[j], acc[i][j]);
        }
        __syncthreads();
    }
#pragma unroll
    for (int i = 0; i < 4; i++) {
        int gm = m0 + ty*4 + i;
        if (gm >= M) continue;
#pragma unroll
        for (int j = 0; j < 4; j++) {
            int gn = n0 + tx*4 + j;
            if (gn < N) C[(long long)gm * ldc + gn] = acc[i][j];
        }
    }
}

// ============ split-bf16 conversion kernels ============
// x = hi + lo with hi = bf16(x), lo = bf16(x - hi).
// C = A_hi B_hi + A_hi B_lo + A_lo B_hi  ==  [hi|hi|lo] @ [hi;lo;hi]  (K = 384)

__global__ void convA_k(const float* __restrict__ proj, __nv_bfloat16* __restrict__ A2)
{
    int idx = blockIdx.x * blockDim.x + threadIdx.x;
    if (idx >= BT_ * E_) return;
    int r = idx >> 7, k = idx & 127;
    float x = proj[idx];
    __nv_bfloat16 hi = __float2bfloat16(x);
    __nv_bfloat16 lo = __float2bfloat16(x - __bfloat162float(hi));
    __nv_bfloat16* row = A2 + (size_t)r * 384;
    row[k]       = hi;
    row[128 + k] = hi;
    row[256 + k] = lo;
}

// transpose + split W_vocab (E=128, V) -> B2t (V, 384) with rows [hi; lo; hi]
__global__ void convB_k(const float* __restrict__ Wv, __nv_bfloat16* __restrict__ B2t)
{
    __shared__ float sh[128][65];
    int n0 = blockIdx.x * 64;
    int tid = threadIdx.x;
    for (int idx = tid; idx < 128 * 64; idx += 256) {
        int k = idx >> 6, n = idx & 63;
        float v = 0.f;
        if (n0 + n < V_) v = Wv[(size_t)k * V_ + n0 + n];
        sh[k][n] = v;
    }
    __syncthreads();
    for (int idx = tid; idx < 64 * 128; idx += 256) {
        int n = idx >> 7, k = idx & 127;
        if (n0 + n >= V_) continue;
        float x = sh[k][n];
        __nv_bfloat16 hi = __float2bfloat16(x);
        __nv_bfloat16 lo = __float2bfloat16(x - __bfloat162float(hi));
        __nv_bfloat16* row = B2t + (size_t)(n0 + n) * 384;
        row[k]       = hi;
        row[128 + k] = lo;
        row[256 + k] = hi;
    }
}

// ============ tensor-core vocab GEMM ============
// C[BT,V] = A2[BT,384] @ B2t[V,384]^T   via mma.sync.m16n8k16 bf16, fp32 accum.
// Block tile 128(M) x 64(N), K-chunk 64, 8 warps in 4(m) x 2(n), warp tile 32x32.
#define MBM 128
#define MBN 64
#define MKC 64
#define ASTR 72   // bf16 stride (pad 8) -> conflict-free 32-bit fragment loads
#define BSTR 72

__global__ void __launch_bounds__(256) vocab_mma_k(
    const __nv_bfloat16* __restrict__ A2,   // (BT, 384) row-major
    const __nv_bfloat16* __restrict__ B2t,  // (V, 384)  row-major (i.e. B col-major)
    float* __restrict__ C)                  // (BT, V)
{
    __shared__ __nv_bfloat16 As[MBM * ASTR];   // 18 KB
    __shared__ __nv_bfloat16 Bs[MBN * BSTR];   //  9 KB
    int m0 = blockIdx.y * MBM;
    int n0 = blockIdx.x * MBN;
    int tid  = threadIdx.x;
    int lane = tid & 31, warp = tid >> 5;
    int wm = warp & 3, wn = warp >> 2;          // 4 x 2 warp grid
    int group = lane >> 2, tig = lane & 3;

    float acc[2][4][4];
#pragma unroll
    for (int i = 0; i < 2; i++)
#pragma unroll
        for (int j = 0; j < 4; j++)
#pragma unroll
            for (int q = 0; q < 4; q++) acc[i][j][q] = 0.f;

    for (int kk = 0; kk < 384; kk += MKC) {
        // A tile: 128 rows x 64 k  (2048 x uint2)
#pragma unroll
        for (int it = 0; it < 8; it++) {
            int li = tid + 256 * it;
            int row = li >> 4, c = (li & 15) << 2;
            uint2 v = *(const uint2*)(A2 + (size_t)(m0 + row) * 384 + kk + c);
            *(uint2*)(As + row * ASTR + c) = v;
        }
        // B tile: 64 rows(n) x 64 k  (1024 x uint2), guard tail of V
#pragma unroll
        for (int it = 0; it < 4; it++) {
            int li = tid + 256 * it;
            int row = li >> 4, c = (li & 15) << 2;
            uint2 v = make_uint2(0u, 0u);
            if (n0 + row < V_)
                v = *(const uint2*)(B2t + (size_t)(n0 + row) * 384 + kk + c);
            *(uint2*)(Bs + row * BSTR + c) = v;
        }
        __syncthreads();

#pragma unroll
        for (int ks = 0; ks < MKC; ks += 16) {
            unsigned af[2][4];
#pragma unroll
            for (int mi = 0; mi < 2; mi++) {
                int r = wm * 32 + mi * 16;
                af[mi][0] = *(const unsigned*)(As + (r + group    ) * ASTR + ks + tig*2    );
                af[mi][1] = *(const unsigned*)(As + (r + group + 8) * ASTR + ks + tig*2    );
                af[mi][2] = *(const unsigned*)(As + (r + group    ) * ASTR + ks + tig*2 + 8);
                af[mi][3] = *(const unsigned*)(As + (r + group + 8) * ASTR + ks + tig*2 + 8);
            }
            unsigned bfr[4][2];
#pragma unroll
            for (int ni = 0; ni < 4; ni++) {
                int n = wn * 32 + ni * 8 + group;
                bfr[ni][0] = *(const unsigned*)(Bs + n * BSTR + ks + tig*2    );
                bfr[ni][1] = *(const unsigned*)(Bs + n * BSTR + ks + tig*2 + 8);
            }
#pragma unroll
            for (int mi = 0; mi < 2; mi++)
#pragma unroll
                for (int ni = 0; ni < 4; ni++) {
                    float* c4 = acc[mi][ni];
                    asm volatile(
                        "mma.sync.aligned.m16n8k16.row.col.f32.bf16.bf16.f32 "
                        "{%0,%1,%2,%3}, {%4,%5,%6,%7}, {%8,%9}, {%0,%1,%2,%3};\n"
                        : "+f"(c4[0]), "+f"(c4[1]), "+f"(c4[2]), "+f"(c4[3])
                        : "r"(af[mi][0]), "r"(af[mi][1]), "r"(af[mi][2]), "r"(af[mi][3]),
                          "r"(bfr[ni][0]), "r"(bfr[ni][1]));
                }
        }
        __syncthreads();
    }

    // epilogue: c0,c1 -> (row=group, col=2*tig,2*tig+1); c2,c3 -> row=group+8
#pragma unroll
    for (int mi = 0; mi < 2; mi++) {
        int r = m0 + wm * 32 + mi * 16 + group;
#pragma unroll
        for (int ni = 0; ni < 4; ni++) {
            int ccol = n0 + wn * 32 + ni * 8 + tig * 2;
            if (ccol < V_) {   // V even, ccol even -> both lanes in range
                float* c4 = acc[mi][ni];
                *(float2*)(C + (size_t)r * V_ + ccol) = make_float2(c4[0], c4[1]);
                *(float2*)(C + (size_t)(r + 8) * V_ + ccol) = make_float2(c4[2], c4[3]);
            }
        }
    }
}

// ---------------- intra-temporal: exp + running-denominator (prefix over t) --------
__global__ void temporal_k(float* __restrict__ e)
{
    int idx = blockIdx.x * blockDim.x + threadIdx.x;
    if (idx >= B_ * L_) return;
    int b = idx / L_, l = idx % L_;
    float* base = e + (size_t)b * T_ * L_ + l;
    float acc = 0.f;
    for (int t = 0; t < T_; t++) {
        float x = __expf(base[(size_t)t * L_]);
        float denom = (t == 0) ? 1.f : acc;
        base[(size_t)t * L_] = x / denom;
        acc += x;
    }
}

// ---------------- normalize enc attention over L (in place) ----------------
__global__ void encnorm_k(float* __restrict__ att)
{
    int r = blockIdx.x;                // BT rows
    float* row = att + (size_t)r * L_;
    float acc = 0.f;
    for (int i = threadIdx.x; i < L_; i += 128) acc += row[i];
    __shared__ float sh[128];
    sh[threadIdx.x] = acc;
    __syncthreads();
    for (int st = 64; st > 0; st >>= 1) {
        if (threadIdx.x < st) sh[threadIdx.x] += sh[threadIdx.x + st];
        __syncthreads();
    }
    float inv = 1.f / sh[0];
    for (int i = threadIdx.x; i < L_; i += 128) row[i] *= inv;
}

// ---------------- masked causal softmax over previous decoder steps ----------------
__global__ void decsm_k(float* __restrict__ s)
{
    int r = blockIdx.x * blockDim.x + threadIdx.x;
    if (r >= BT_) return;
    int t = r % T_;
    float* row = s + (size_t)r * T_;
    if (t == 0) {
        for (int j = 0; j < T_; j++) row[j] = 0.f;   // dec_ctx forced 0 at t=0
        return;
    }
    float m = -1e30f;
    for (int j = 0; j < t; j++) m = fmaxf(m, row[j]);
    float sum = 0.f;
    for (int j = 0; j < t; j++) { float e = __expf(row[j] - m); row[j] = e; sum += e; }
    float inv = 1.f / sum;
    for (int j = 0; j < t; j++) row[j] *= inv;
    for (int j = t; j < T_; j++) row[j] = 0.f;
}

// ---------------- copy h into cat[:, 0:H2] ----------------
__global__ void copyh_k(const float* __restrict__ dec, float* __restrict__ cat)
{
    int idx = blockIdx.x * blockDim.x + threadIdx.x;
    if (idx >= BT_ * H2_) return;
    int r = idx >> 9, h = idx & 511;
    cat[(size_t)r * (3*H2_) + h] = dec[idx];
}

// ---------------- copy gate p = sigmoid(cat . w_ptr + b) ----------------
__global__ void pgate_k(const float* __restrict__ cat, const float* __restrict__ w,
                        const float* __restrict__ bb, float* __restrict__ p)
{
    int r = blockIdx.x;
    const float* row = cat + (size_t)r * (3*H2_);
    float acc = 0.f;
    for (int i = threadIdx.x; i < 3*H2_; i += 256) acc += row[i] * w[i];
    __shared__ float sh[256];
    sh[threadIdx.x] = acc;
    __syncthreads();
    for (int st = 128; st > 0; st >>= 1) {
        if (threadIdx.x < st) sh[threadIdx.x] += sh[threadIdx.x + st];
        __syncthreads();
    }
    if (threadIdx.x == 0) p[r] = 1.f / (1.f + __expf(-(sh[0] + bb[0])));
}

// ---------------- online row max / sum-exp over V (one pass) ----------------
__global__ void rowstats_k(const float* __restrict__ logits,
                           float* __restrict__ rmax, float* __restrict__ rsum)
{
    int r = blockIdx.x;
    const float4* row = (const float4*)(logits + (size_t)r * V_);
    float m = -1e30f, s = 0.f;
    for (int i = threadIdx.x; i < V_/4; i += blockDim.x) {
        float4 x4 = row[i];
        float xs[4] = {x4.x, x4.y, x4.z, x4.w};
#pragma unroll
        for (int j = 0; j < 4; j++) {
            float x = xs[j];
            if (x > m) { s = s * __expf(m - x) + 1.f; m = x; }
            else       { s += __expf(x - m); }
        }
    }
    __shared__ float sm[256], ss[256];
    sm[threadIdx.x] = m; ss[threadIdx.x] = s;
    __syncthreads();
    for (int st = 128; st > 0; st >>= 1) {
        if (threadIdx.x < st) {
            float m1 = sm[threadIdx.x], s1 = ss[threadIdx.x];
            float m2 = sm[threadIdx.x + st], s2 = ss[threadIdx.x + st];
            float M = fmaxf(m1, m2);
            sm[threadIdx.x] = M;
            ss[threadIdx.x] = s1 * __expf(m1 - M) + s2 * __expf(m2 - M);
        }
        __syncthreads();
    }
    if (threadIdx.x == 0) { rmax[r] = sm[0]; rsum[r] = ss[0]; }
}

// ---------------- final write: (1-p)*softmax into [:, :V], zero OOV tail ----------
__global__ void final_k(const float* __restrict__ logits, const float* __restrict__ rmax,
                        const float* __restrict__ rsum, const float* __restrict__ p,
                        float* __restrict__ out)
{
    int r = blockIdx.y;
    int v4 = blockIdx.x * blockDim.x + threadIdx.x;     // float4 index
    if (v4 >= VEXT_/4) return;
    float4 o = make_float4(0.f, 0.f, 0.f, 0.f);
    if (v4 < V_/4) {
        float sc = (1.f - p[r]) / rsum[r];
        float mx = rmax[r];
        float4 x = *(const float4*)(logits + (size_t)r * V_ + v4*4);
        o.x = sc * __expf(x.x - mx);
        o.y = sc * __expf(x.y - mx);
        o.z = sc * __expf(x.z - mx);
        o.w = sc * __expf(x.w - mx);
    }
    *(float4*)(out + (size_t)r * VEXT_ + v4*4) = o;
}

// ---------------- pointer scatter-add: out[r, ev[b,l]] += p[r]*enc_att[r,l] -------
__global__ void scatter_k(const int* __restrict__ ev, const float* __restrict__ att,
                          const float* __restrict__ p, float* __restrict__ out)
{
    int idx = blockIdx.x * blockDim.x + threadIdx.x;
    if (idx >= BT_ * L_) return;
    int l = idx % L_;
    int r = idx / L_;         // r = b*T + t
    int b = r / T_;
    float val = p[r] * att[idx];
    atomicAdd(&out[(size_t)r * VEXT_ + ev[b * L_ + l]], val);
}

// ---------------- host orchestration ----------------
static void gemm(int M, int N, int K,
                 const float* A, int lda, long long sA,
                 const float* B, int ldb, long long sB, int transB,
                 float* C, int ldc, long long sC, int batch)
{
    dim3 grid((N + TN - 1) / TN, (M + TM - 1) / TM, batch);
    gemm_k<<<grid, 256>>>(M, N, K, A, lda, sA, B, ldb, sB, transB, C, ldc, sC);
}

extern "C" void kernel_launch(void* const* d_in, const int* in_sizes, int n_in,
                              void* d_out, int out_size)
{
    const float* dec     = (const float*)d_in[0];   // (B,T,H2)
    const float* enc     = (const float*)d_in[1];   // (B,L,H2)
    const float* W_enc   = (const float*)d_in[2];   // (H2,H2)
    const float* W_dec   = (const float*)d_in[3];   // (H2,H2)
    const float* W_proj  = (const float*)d_in[4];   // (3H2,E)
    const float* W_vocab = (const float*)d_in[5];   // (E,V)
    const float* w_ptr   = (const float*)d_in[6];   // (3H2,)
    const float* b_ptr   = (const float*)d_in[7];   // (1,)
    const int*   ev      = (const int*)d_in[8];     // (B,L)
    float* out = (float*)d_out;                     // (B,T,VEXT)

    float *Xe, *Xd, *att, *s, *cat, *proj, *p, *rmax, *rsum, *logits;
    __nv_bfloat16 *A2, *B2t;
    cudaGetSymbolAddress((void**)&Xe,     g_Xe);
    cudaGetSymbolAddress((void**)&Xd,     g_Xd);
    cudaGetSymbolAddress((void**)&att,    g_att);
    cudaGetSymbolAddress((void**)&s,      g_s);
    cudaGetSymbolAddress((void**)&cat,    g_cat);
    cudaGetSymbolAddress((void**)&proj,   g_proj);
    cudaGetSymbolAddress((void**)&p,      g_p);
    cudaGetSymbolAddress((void**)&rmax,   g_rmax);
    cudaGetSymbolAddress((void**)&rsum,   g_rsum);
    cudaGetSymbolAddress((void**)&logits, g_logits);
    cudaGetSymbolAddress((void**)&A2,     g_A2);
    cudaGetSymbolAddress((void**)&B2t,    g_B2t);

    // 0) split/transpose W_vocab early (independent of everything else)
    convB_k<<<(V_ + 63) / 64, 256>>>(W_vocab, B2t);

    // 1) bilinear projections of decoder hiddens
    gemm(BT_, H2_, H2_, dec, H2_, 0, W_enc, H2_, 0, 0, Xe, H2_, 0, 1);
    gemm(BT_, H2_, H2_, dec, H2_, 0, W_dec, H2_, 0, 0, Xd, H2_, 0, 1);

    // 2) encoder attention scores e[b,t,l] = Xe[b,t,:] . enc[b,l,:]   (batched, B^T)
    gemm(T_, L_, H2_, Xe, H2_, (long long)T_*H2_,
         enc, H2_, (long long)L_*H2_, 1,
         att, L_, (long long)T_*L_, B_);

    // 3) intra-temporal exp + cumulative denominator, then normalize over L
    temporal_k<<<(B_*L_ + 255)/256, 256>>>(att);
    encnorm_k<<<BT_, 128>>>(att);

    // 4) decoder self-attention scores + causal softmax
    gemm(T_, T_, H2_, Xd, H2_, (long long)T_*H2_,
         dec, H2_, (long long)T_*H2_, 1,
         s, T_, (long long)T_*T_, B_);
    decsm_k<<<(BT_ + 127)/128, 128>>>(s);

    // 5) assemble cat = [h | enc_ctx | dec_ctx]
    copyh_k<<<(BT_*H2_ + 255)/256, 256>>>(dec, cat);
    gemm(T_, H2_, L_, att, L_, (long long)T_*L_,
         enc, H2_, (long long)L_*H2_, 0,
         cat + H2_, 3*H2_, (long long)T_*3*H2_, B_);
    gemm(T_, H2_, T_, s, T_, (long long)T_*T_,
         dec, H2_, (long long)T_*H2_, 0,
         cat + 2*H2_, 3*H2_, (long long)T_*3*H2_, B_);

    // 6) copy gate + embedding projection
    pgate_k<<<BT_, 256>>>(cat, w_ptr, b_ptr, p);
    gemm(BT_, E_, 3*H2_, cat, 3*H2_, 0, W_proj, E_, 0, 0, proj, E_, 0, 1);

    // 7) vocab logits via tensor cores: split A, then K=384 bf16 MMA GEMM
    convA_k<<<(BT_*E_ + 255)/256, 256>>>(proj, A2);
    {
        dim3 grid((V_ + MBN - 1) / MBN, BT_ / MBM);
        vocab_mma_k<<<grid, 256>>>(A2, B2t, logits);
    }

    // 8) softmax stats, final distribution write, pointer scatter
    rowstats_k<<<BT_, 256>>>(logits, rmax, rsum);
    final_k<<<dim3((VEXT_/4 + 255)/256, BT_), 256>>>(logits, rmax, rsum, p, out);
    scatter_k<<<(BT_*L_ + 255)/256, 256>>>(ev, att, p, out);
}

// round 7
// speedup vs baseline: 2.2832x; 1.1014x over previous
#include <cuda_runtime.h>
#include <cuda_bf16.h>
#include <math.h>

#define B_   32
#define T_   48
#define L_   400
#define H2_  512
#define E_   128
#define V_   50000
#define OOV_ 100
#define VEXT_ 50100
#define BT_  (B_*T_)

// ---------------- scratch (static device allocations; no cudaMalloc) ----------------
__device__ float g_Xe[BT_*H2_];
__device__ float g_Xd[BT_*H2_];
__device__ float g_att[BT_*L_];        // e -> temporal -> enc_att (in place)
__device__ float g_s[BT_*T_];          // dec scores -> datt (in place)
__device__ float g_cat[BT_*3*H2_];     // [h | enc_ctx | dec_ctx]
__device__ float g_proj[BT_*E_];
__device__ float g_p[BT_];
__device__ float g_rmax[BT_];
__device__ float g_rsum[BT_];
__device__ float g_logits[(size_t)BT_*V_];            // 307 MB
__device__ __nv_bfloat16 g_A2[(size_t)BT_*3*E_];      // split A: [hi|hi|lo], (BT,384)
__device__ __nv_bfloat16 g_B2t[(size_t)V_*3*E_];      // split B^T: rows [hi;lo;hi], (V,384)

// ---------------- generic tiled fp32 GEMM with register prefetch ----------------
#define TM 64
#define TN 64
#define TKK 16

__global__ void gemm_k(int M, int N, int K,
                       const float* __restrict__ A, int lda, long long sA,
                       const float* __restrict__ B, int ldb, long long sB, int transB,
                       float* __restrict__ C, int ldc, long long sC)
{
    __shared__ float As[TKK][TM];
    __shared__ float Bs[TKK][TN];
    int bz = blockIdx.z;
    A += (long long)bz * sA;
    B += (long long)bz * sB;
    C += (long long)bz * sC;
    int m0 = blockIdx.y * TM;
    int n0 = blockIdx.x * TN;
    int tid = threadIdx.x;          // 0..255
    int tx = tid & 15, ty = tid >> 4;
    float acc[4][4] = {};
    float ar[4], br[4];

    // prologue: load chunk 0 into registers
#pragma unroll
    for (int i = 0; i < 4; i++) {
        int li = tid + 256 * i;
        int m = li & 63, k = li >> 6;
        int gm = m0 + m, gk = k;
        ar[i] = (gm < M && gk < K) ? A[(long long)gm * lda + gk] : 0.f;
    }
#pragma unroll
    for (int i = 0; i < 4; i++) {
        int li = tid + 256 * i;
        int n = li & 63, k = li >> 6;
        int gn = n0 + n, gk = k;
        float v = 0.f;
        if (gn < N && gk < K)
            v = transB ? B[(long long)gn * ldb + gk] : B[(long long)gk * ldb + gn];
        br[i] = v;
    }

    for (int kk = 0; kk < K; kk += TKK) {
        // commit current chunk to shared
#pragma unroll
        for (int i = 0; i < 4; i++) { int li = tid + 256*i; As[li>>6][li&63] = ar[i]; }
#pragma unroll
        for (int i = 0; i < 4; i++) { int li = tid + 256*i; Bs[li>>6][li&63] = br[i]; }
        __syncthreads();

        // prefetch next chunk (LDG latency overlapped with compute below)
        int kn = kk + TKK;
        if (kn < K) {
#pragma unroll
            for (int i = 0; i < 4; i++) {
                int li = tid + 256 * i;
                int m = li & 63, k = li >> 6;
                int gm = m0 + m, gk = kn + k;
                ar[i] = (gm < M && gk < K) ? A[(long long)gm * lda + gk] : 0.f;
            }
#pragma unroll
            for (int i = 0; i < 4; i++) {
                int li = tid + 256 * i;
                int n = li & 63, k = li >> 6;
                int gn = n0 + n, gk = kn + k;
                float v = 0.f;
                if (gn < N && gk < K)
                    v = transB ? B[(long long)gn * ldb + gk] : B[(long long)gk * ldb + gn];
                br[i] = v;
            }
        }

#pragma unroll
        for (int k = 0; k < TKK; k++) {
            float a0[4], b0[4];
#pragma unroll
            for (int i = 0; i < 4; i++) a0[i] = As[k][ty*4 + i];
#pragma unroll
            for (int j = 0; j < 4; j++) b0[j] = Bs[k][tx*4 + j];
#pragma unroll
            for (int i = 0; i < 4; i++)
#pragma unroll
                for (int j = 0; j < 4; j++)
                    acc[i][j] = fmaf(a0[i], b0[j], acc[i][j]);
        }
        __syncthreads();
    }
#pragma unroll
    for (int i = 0; i < 4; i++) {
        int gm = m0 + ty*4 + i;
        if (gm >= M) continue;
#pragma unroll
        for (int j = 0; j < 4; j++) {
            int gn = n0 + tx*4 + j;
            if (gn < N) C[(long long)gm * ldc + gn] = acc[i][j];
        }
    }
}

// ============ split-bf16 conversion kernels ============
__global__ void convA_k(const float* __restrict__ proj, __nv_bfloat16* __restrict__ A2)
{
    int idx = blockIdx.x * blockDim.x + threadIdx.x;
    if (idx >= BT_ * E_) return;
    int r = idx >> 7, k = idx & 127;
    float x = proj[idx];
    __nv_bfloat16 hi = __float2bfloat16(x);
    __nv_bfloat16 lo = __float2bfloat16(x - __bfloat162float(hi));
    __nv_bfloat16* row = A2 + (size_t)r * 384;
    row[k]       = hi;
    row[128 + k] = hi;
    row[256 + k] = lo;
}

__global__ void convB_k(const float* __restrict__ Wv, __nv_bfloat16* __restrict__ B2t)
{
    __shared__ float sh[128][65];
    int n0 = blockIdx.x * 64;
    int tid = threadIdx.x;
    for (int idx = tid; idx < 128 * 64; idx += 256) {
        int k = idx >> 6, n = idx & 63;
        float v = 0.f;
        if (n0 + n < V_) v = Wv[(size_t)k * V_ + n0 + n];
        sh[k][n] = v;
    }
    __syncthreads();
    for (int idx = tid; idx < 64 * 128; idx += 256) {
        int n = idx >> 7, k = idx & 127;
        if (n0 + n >= V_) continue;
        float x = sh[k][n];
        __nv_bfloat16 hi = __float2bfloat16(x);
        __nv_bfloat16 lo = __float2bfloat16(x - __bfloat162float(hi));
        __nv_bfloat16* row = B2t + (size_t)(n0 + n) * 384;
        row[k]       = hi;
        row[128 + k] = lo;
        row[256 + k] = hi;
    }
}

// ============ tensor-core vocab GEMM (double-buffered) ============
// C[BT,V] = A2[BT,384] @ B2t[V,384]^T, mma.m16n8k16 bf16.
// Block 128(M) x 64(N); K-chunk 32 (12 chunks); smem ping-pong; uint4 gmem loads.
#define MBM 128
#define MBN 64
#define MKC 32
#define MST 40          // bf16 smem stride (32 + 8 pad): 80B rows, 16B aligned, conflict-free
#define NCHUNK 12

__global__ void __launch_bounds__(256) vocab_mma_k(
    const __nv_bfloat16* __restrict__ A2,   // (BT, 384) row-major
    const __nv_bfloat16* __restrict__ B2t,  // (V, 384)  row-major
    float* __restrict__ C)                  // (BT, V)
{
    __shared__ __nv_bfloat16 As[2][MBM * MST];   // 2 x 10 KB
    __shared__ __nv_bfloat16 Bs[2][MBN * MST];   // 2 x  5 KB
    int m0 = blockIdx.y * MBM;
    int n0 = blockIdx.x * MBN;
    int tid  = threadIdx.x;
    int lane = tid & 31, warp = tid >> 5;
    int wm = warp & 3, wn = warp >> 2;          // 4 x 2 warp grid, warp tile 32x32
    int group = lane >> 2, tig = lane & 3;

    // per-thread global load slots: A = 2 uint4, B = 1 uint4
    int arow0 = tid >> 2,        ac0 = (tid & 3) << 3;         // rows 0..63
    int arow1 = (tid + 256) >> 2, ac1 = ac0;                   // rows 64..127
    int brow  = tid >> 2,        bc  = (tid & 3) << 3;         // rows 0..63
    int bguard = (n0 + brow < V_);

    float acc[2][4][4];
#pragma unroll
    for (int i = 0; i < 2; i++)
#pragma unroll
        for (int j = 0; j < 4; j++)
#pragma unroll
            for (int q = 0; q < 4; q++) acc[i][j][q] = 0.f;

    uint4 ra0, ra1, rb;
    // prologue: load chunk 0
    ra0 = *(const uint4*)(A2 + (size_t)(m0 + arow0) * 384 + ac0);
    ra1 = *(const uint4*)(A2 + (size_t)(m0 + arow1) * 384 + ac1);
    rb  = make_uint4(0u,0u,0u,0u);
    if (bguard) rb = *(const uint4*)(B2t + (size_t)(n0 + brow) * 384 + bc);
    *(uint4*)(As[0] + arow0 * MST + ac0) = ra0;
    *(uint4*)(As[0] + arow1 * MST + ac1) = ra1;
    *(uint4*)(Bs[0] + brow  * MST + bc ) = rb;
    __syncthreads();

    for (int c = 0; c < NCHUNK; c++) {
        int buf = c & 1;
        int kn = (c + 1) * MKC;
        if (c + 1 < NCHUNK) {
            ra0 = *(const uint4*)(A2 + (size_t)(m0 + arow0) * 384 + kn + ac0);
            ra1 = *(const uint4*)(A2 + (size_t)(m0 + arow1) * 384 + kn + ac1);
            if (bguard) rb = *(const uint4*)(B2t + (size_t)(n0 + brow) * 384 + kn + bc);
        }

        const __nv_bfloat16* Ab = As[buf];
        const __nv_bfloat16* Bb = Bs[buf];
#pragma unroll
        for (int ks = 0; ks < MKC; ks += 16) {
            unsigned af[2][4];
#pragma unroll
            for (int mi = 0; mi < 2; mi++) {
                int r = wm * 32 + mi * 16;
                af[mi][0] = *(const unsigned*)(Ab + (r + group    ) * MST + ks + tig*2    );
                af[mi][1] = *(const unsigned*)(Ab + (r + group + 8) * MST + ks + tig*2    );
                af[mi][2] = *(const unsigned*)(Ab + (r + group    ) * MST + ks + tig*2 + 8);
                af[mi][3] = *(const unsigned*)(Ab + (r + group + 8) * MST + ks + tig*2 + 8);
            }
            unsigned bfr[4][2];
#pragma unroll
            for (int ni = 0; ni < 4; ni++) {
                int n = wn * 32 + ni * 8 + group;
                bfr[ni][0] = *(const unsigned*)(Bb + n * MST + ks + tig*2    );
                bfr[ni][1] = *(const unsigned*)(Bb + n * MST + ks + tig*2 + 8);
            }
#pragma unroll
            for (int mi = 0; mi < 2; mi++)
#pragma unroll
                for (int ni = 0; ni < 4; ni++) {
                    float* c4 = acc[mi][ni];
                    asm volatile(
                        "mma.sync.aligned.m16n8k16.row.col.f32.bf16.bf16.f32 "
                        "{%0,%1,%2,%3}, {%4,%5,%6,%7}, {%8,%9}, {%0,%1,%2,%3};\n"
                        : "+f"(c4[0]), "+f"(c4[1]), "+f"(c4[2]), "+f"(c4[3])
                        : "r"(af[mi][0]), "r"(af[mi][1]), "r"(af[mi][2]), "r"(af[mi][3]),
                          "r"(bfr[ni][0]), "r"(bfr[ni][1]));
                }
        }

        if (c + 1 < NCHUNK) {
            int nb = 1 - buf;
            *(uint4*)(As[nb] + arow0 * MST + ac0) = ra0;
            *(uint4*)(As[nb] + arow1 * MST + ac1) = ra1;
            *(uint4*)(Bs[nb] + brow  * MST + bc ) = rb;
            __syncthreads();
        }
    }

#pragma unroll
    for (int mi = 0; mi < 2; mi++) {
        int r = m0 + wm * 32 + mi * 16 + group;
#pragma unroll
        for (int ni = 0; ni < 4; ni++) {
            int ccol = n0 + wn * 32 + ni * 8 + tig * 2;
            if (ccol < V_) {
                float* c4 = acc[mi][ni];
                *(float2*)(C + (size_t)r * V_ + ccol) = make_float2(c4[0], c4[1]);
                *(float2*)(C + (size_t)(r + 8) * V_ + ccol) = make_float2(c4[2], c4[3]);
            }
        }
    }
}

// ---------------- intra-temporal: exp + running-denominator (float4 chains) -------
__global__ void temporal_k(float* __restrict__ e)
{
    int idx = blockIdx.x * blockDim.x + threadIdx.x;    // over B * L/4
    if (idx >= B_ * (L_/4)) return;
    int b = idx / (L_/4), l4 = idx % (L_/4);
    float* base = e + (size_t)b * T_ * L_ + l4 * 4;
    float4 acc = make_float4(0.f, 0.f, 0.f, 0.f);
    for (int t = 0; t < T_; t++) {
        float4 x = *(float4*)(base + (size_t)t * L_);
        float4 ex;
        ex.x = __expf(x.x); ex.y = __expf(x.y); ex.z = __expf(x.z); ex.w = __expf(x.w);
        float4 o;
        if (t == 0) o = ex;
        else {
            o.x = ex.x / acc.x; o.y = ex.y / acc.y;
            o.z = ex.z / acc.z; o.w = ex.w / acc.w;
        }
        *(float4*)(base + (size_t)t * L_) = o;
        acc.x += ex.x; acc.y += ex.y; acc.z += ex.z; acc.w += ex.w;
    }
}

// ---------------- normalize enc attention over L (in place) ----------------
__global__ void encnorm_k(float* __restrict__ att)
{
    int r = blockIdx.x;                // BT rows
    float* row = att + (size_t)r * L_;
    float acc = 0.f;
    for (int i = threadIdx.x; i < L_; i += 128) acc += row[i];
    __shared__ float sh[128];
    sh[threadIdx.x] = acc;
    __syncthreads();
    for (int st = 64; st > 0; st >>= 1) {
        if (threadIdx.x < st) sh[threadIdx.x] += sh[threadIdx.x + st];
        __syncthreads();
    }
    float inv = 1.f / sh[0];
    for (int i = threadIdx.x; i < L_; i += 128) row[i] *= inv;
}

// ---------------- masked causal softmax over previous decoder steps ----------------
__global__ void decsm_k(float* __restrict__ s)
{
    int r = blockIdx.x * blockDim.x + threadIdx.x;
    if (r >= BT_) return;
    int t = r % T_;
    float* row = s + (size_t)r * T_;
    if (t == 0) {
        for (int j = 0; j < T_; j++) row[j] = 0.f;   // dec_ctx forced 0 at t=0
        return;
    }
    float m = -1e30f;
    for (int j = 0; j < t; j++) m = fmaxf(m, row[j]);
    float sum = 0.f;
    for (int j = 0; j < t; j++) { float e = __expf(row[j] - m); row[j] = e; sum += e; }
    float inv = 1.f / sum;
    for (int j = 0; j < t; j++) row[j] *= inv;
    for (int j = t; j < T_; j++) row[j] = 0.f;
}

// ---------------- copy h into cat[:, 0:H2] ----------------
__global__ void copyh_k(const float* __restrict__ dec, float* __restrict__ cat)
{
    int idx = blockIdx.x * blockDim.x + threadIdx.x;
    if (idx >= BT_ * H2_) return;
    int r = idx >> 9, h = idx & 511;
    cat[(size_t)r * (3*H2_) + h] = dec[idx];
}

// ---------------- copy gate p = sigmoid(cat . w_ptr + b) ----------------
__global__ void pgate_k(const float* __restrict__ cat, const float* __restrict__ w,
                        const float* __restrict__ bb, float* __restrict__ p)
{
    int r = blockIdx.x;
    const float* row = cat + (size_t)r * (3*H2_);
    float acc = 0.f;
    for (int i = threadIdx.x; i < 3*H2_; i += 256) acc += row[i] * w[i];
    __shared__ float sh[256];
    sh[threadIdx.x] = acc;
    __syncthreads();
    for (int st = 128; st > 0; st >>= 1) {
        if (threadIdx.x < st) sh[threadIdx.x] += sh[threadIdx.x + st];
        __syncthreads();
    }
    if (threadIdx.x == 0) p[r] = 1.f / (1.f + __expf(-(sh[0] + bb[0])));
}

// ---------------- online row max / sum-exp over V (one pass) ----------------
__global__ void rowstats_k(const float* __restrict__ logits,
                           float* __restrict__ rmax, float* __restrict__ rsum)
{
    int r = blockIdx.x;
    const float4* row = (const float4*)(logits + (size_t)r * V_);
    float m = -1e30f, s = 0.f;
    for (int i = threadIdx.x; i < V_/4; i += blockDim.x) {
        float4 x4 = row[i];
        float xs[4] = {x4.x, x4.y, x4.z, x4.w};
#pragma unroll
        for (int j = 0; j < 4; j++) {
            float x = xs[j];
            if (x > m) { s = s * __expf(m - x) + 1.f; m = x; }
            else       { s += __expf(x - m); }
        }
    }
    __shared__ float sm[256], ss[256];
    sm[threadIdx.x] = m; ss[threadIdx.x] = s;
    __syncthreads();
    for (int st = 128; st > 0; st >>= 1) {
        if (threadIdx.x < st) {
            float m1 = sm[threadIdx.x], s1 = ss[threadIdx.x];
            float m2 = sm[threadIdx.x + st], s2 = ss[threadIdx.x + st];
            float M = fmaxf(m1, m2);
            sm[threadIdx.x] = M;
            ss[threadIdx.x] = s1 * __expf(m1 - M) + s2 * __expf(m2 - M);
        }
        __syncthreads();
    }
    if (threadIdx.x == 0) { rmax[r] = sm[0]; rsum[r] = ss[0]; }
}

// ---------------- final write: (1-p)*softmax into [:, :V], zero OOV tail ----------
__global__ void final_k(const float* __restrict__ logits, const float* __restrict__ rmax,
                        const float* __restrict__ rsum, const float* __restrict__ p,
                        float* __restrict__ out)
{
    int r = blockIdx.y;
    int v4 = blockIdx.x * blockDim.x + threadIdx.x;     // float4 index
    if (v4 >= VEXT_/4) return;
    float4 o = make_float4(0.f, 0.f, 0.f, 0.f);
    if (v4 < V_/4) {
        float sc = (1.f - p[r]) / rsum[r];
        float mx = rmax[r];
        float4 x = *(const float4*)(logits + (size_t)r * V_ + v4*4);
        o.x = sc * __expf(x.x - mx);
        o.y = sc * __expf(x.y - mx);
        o.z = sc * __expf(x.z - mx);
        o.w = sc * __expf(x.w - mx);
    }
    *(float4*)(out + (size_t)r * VEXT_ + v4*4) = o;
}

// ---------------- pointer scatter-add: out[r, ev[b,l]] += p[r]*enc_att[r,l] -------
__global__ void scatter_k(const int* __restrict__ ev, const float* __restrict__ att,
                          const float* __restrict__ p, float* __restrict__ out)
{
    int idx = blockIdx.x * blockDim.x + threadIdx.x;
    if (idx >= BT_ * L_) return;
    int l = idx % L_;
    int r = idx / L_;         // r = b*T + t
    int b = r / T_;
    float val = p[r] * att[idx];
    atomicAdd(&out[(size_t)r * VEXT_ + ev[b * L_ + l]], val);
}

// ---------------- host orchestration ----------------
static void gemm(int M, int N, int K,
                 const float* A, int lda, long long sA,
                 const float* B, int ldb, long long sB, int transB,
                 float* C, int ldc, long long sC, int batch)
{
    dim3 grid((N + TN - 1) / TN, (M + TM - 1) / TM, batch);
    gemm_k<<<grid, 256>>>(M, N, K, A, lda, sA, B, ldb, sB, transB, C, ldc, sC);
}

extern "C" void kernel_launch(void* const* d_in, const int* in_sizes, int n_in,
                              void* d_out, int out_size)
{
    const float* dec     = (const float*)d_in[0];   // (B,T,H2)
    const float* enc     = (const float*)d_in[1];   // (B,L,H2)
    const float* W_enc   = (const float*)d_in[2];   // (H2,H2)
    const float* W_dec   = (const float*)d_in[3];   // (H2,H2)
    const float* W_proj  = (const float*)d_in[4];   // (3H2,E)
    const float* W_vocab = (const float*)d_in[5];   // (E,V)
    const float* w_ptr   = (const float*)d_in[6];   // (3H2,)
    const float* b_ptr   = (const float*)d_in[7];   // (1,)
    const int*   ev      = (const int*)d_in[8];     // (B,L)
    float* out = (float*)d_out;                     // (B,T,VEXT)

    float *Xe, *Xd, *att, *s, *cat, *proj, *p, *rmax, *rsum, *logits;
    __nv_bfloat16 *A2, *B2t;
    cudaGetSymbolAddress((void**)&Xe,     g_Xe);
    cudaGetSymbolAddress((void**)&Xd,     g_Xd);
    cudaGetSymbolAddress((void**)&att,    g_att);
    cudaGetSymbolAddress((void**)&s,      g_s);
    cudaGetSymbolAddress((void**)&cat,    g_cat);
    cudaGetSymbolAddress((void**)&proj,   g_proj);
    cudaGetSymbolAddress((void**)&p,      g_p);
    cudaGetSymbolAddress((void**)&rmax,   g_rmax);
    cudaGetSymbolAddress((void**)&rsum,   g_rsum);
    cudaGetSymbolAddress((void**)&logits, g_logits);
    cudaGetSymbolAddress((void**)&A2,     g_A2);
    cudaGetSymbolAddress((void**)&B2t,    g_B2t);

    // 0) split/transpose W_vocab early (independent of everything else)
    convB_k<<<(V_ + 63) / 64, 256>>>(W_vocab, B2t);

    // 1) bilinear projections of decoder hiddens
    gemm(BT_, H2_, H2_, dec, H2_, 0, W_enc, H2_, 0, 0, Xe, H2_, 0, 1);
    gemm(BT_, H2_, H2_, dec, H2_, 0, W_dec, H2_, 0, 0, Xd, H2_, 0, 1);

    // 2) encoder attention scores e[b,t,l] = Xe[b,t,:] . enc[b,l,:]   (batched, B^T)
    gemm(T_, L_, H2_, Xe, H2_, (long long)T_*H2_,
         enc, H2_, (long long)L_*H2_, 1,
         att, L_, (long long)T_*L_, B_);

    // 3) intra-temporal exp + cumulative denominator, then normalize over L
    temporal_k<<<(B_*(L_/4) + 255)/256, 256>>>(att);
    encnorm_k<<<BT_, 128>>>(att);

    // 4) decoder self-attention scores + causal softmax
    gemm(T_, T_, H2_, Xd, H2_, (long long)T_*H2_,
         dec, H2_, (long long)T_*H2_, 1,
         s, T_, (long long)T_*T_, B_);
    decsm_k<<<(BT_ + 127)/128, 128>>>(s);

    // 5) assemble cat = [h | enc_ctx | dec_ctx]
    copyh_k<<<(BT_*H2_ + 255)/256, 256>>>(dec, cat);
    gemm(T_, H2_, L_, att, L_, (long long)T_*L_,
         enc, H2_, (long long)L_*H2_, 0,
         cat + H2_, 3*H2_, (long long)T_*3*H2_, B_);
    gemm(T_, H2_, T_, s, T_, (long long)T_*T_,
         dec, H2_, (long long)T_*H2_, 0,
         cat + 2*H2_, 3*H2_, (long long)T_*3*H2_, B_);

    // 6) copy gate + embedding projection
    pgate_k<<<BT_, 256>>>(cat, w_ptr, b_ptr, p);
    gemm(BT_, E_, 3*H2_, cat, 3*H2_, 0, W_proj, E_, 0, 0, proj, E_, 0, 1);

    // 7) vocab logits via tensor cores: split A, then K=384 bf16 MMA GEMM
    convA_k<<<(BT_*E_ + 255)/256, 256>>>(proj, A2);
    {
        dim3 grid((V_ + MBN - 1) / MBN, BT_ / MBM);
        vocab_mma_k<<<grid, 256>>>(A2, B2t, logits);
    }

    // 8) softmax stats, final distribution write, pointer scatter
    rowstats_k<<<BT_, 256>>>(logits, rmax, rsum);
    final_k<<<dim3((VEXT_/4 + 255)/256, BT_), 256>>>(logits, rmax, rsum, p, out);
    scatter_k<<<(BT_*L_ + 255)/256, 256>>>(ev, att, p, out);
}